// round 11
// baseline (speedup 1.0000x reference)
#include <cuda_runtime.h>

#define T_STEPS 10
#define B_SZ    32
#define CIN     3
#define COUT    64
#define SPAT    4096            // 64*64
#define N_THR   (T_STEPS * COUT)
#define DECAY   0.2f
#define INH     1.625f
#define KC      4.6166241f      /* 3.2 * log2(e) */

// Scratch: conv results, CHANNEL-LAST layout (t, b, sp, c).  335.5 MB
__device__ float    g_i[T_STEPS * B_SZ * SPAT * COUT];
__device__ unsigned g_thr_keys[N_THR];

// ---------------------------------------------------------------------------
__global__ void init_keys() {
    int i = blockIdx.x * blockDim.x + threadIdx.x;
    if (i < N_THR) g_thr_keys[i] = 0u;   // key 0 == very negative float
}

// ---------------------------------------------------------------------------
// Conv 3x3, stride 1, pad 1 (R10, proven at the FFMA floor). LANE =
// CHANNEL-PAIR with register weights and a sliding 3x3x3 input window;
// float2 stores -> natively coalesced channel-last output.
#define STEP(S0_, S1_, S2_, C_, DOLOAD_) do {                                 \
    float a0 = 0.f, a1 = 0.f, a2 = 0.f, b0 = 0.f, b1 = 0.f, b2 = 0.f;         \
    const int SL_[3] = {S0_, S1_, S2_};                                       \
    _Pragma("unroll")                                                         \
    for (int ky = 0; ky < 3; ky++)                                            \
        _Pragma("unroll")                                                     \
        for (int kx = 0; kx < 3; kx++) {                                      \
            const int j = ky * 3 + kx;                                        \
            const int s = SL_[kx];                                            \
            a0 = fmaf(xw[0][s][ky], w0[j],      a0);                          \
            a1 = fmaf(xw[1][s][ky], w0[j + 9],  a1);                          \
            a2 = fmaf(xw[2][s][ky], w0[j + 18], a2);                          \
            b0 = fmaf(xw[0][s][ky], w1[j],      b0);                          \
            b1 = fmaf(xw[1][s][ky], w1[j + 9],  b1);                          \
            b2 = fmaf(xw[2][s][ky], w1[j + 18], b2);                          \
        }                                                                     \
    const float v0 = (a0 + a1) + a2;                                          \
    const float v1 = (b0 + b1) + b2;                                          \
    gp[sprow + (C_) * 32 + tx] = make_float2(v0, v1);                         \
    mx0 = fmaxf(mx0, v0);                                                     \
    mx1 = fmaxf(mx1, v1);                                                     \
    if (DOLOAD_) {                                                            \
        _Pragma("unroll")                                                     \
        for (int ci = 0; ci < CIN; ci++)                                      \
            _Pragma("unroll")                                                 \
            for (int ky = 0; ky < 3; ky++)                                    \
                xw[ci][S0_][ky] = xs[ci][row + ky][(C_) + 3];                 \
    }                                                                         \
} while (0)

__global__ void __launch_bounds__(128) conv_kernel(const float* __restrict__ x,
                                                   const float* __restrict__ Wt) {
    __shared__ float    xs[CIN][18][34];     // 32x16 tile + halo
    __shared__ float    ws[COUT * 28];       // 27 weights + 1 pad per channel
    __shared__ unsigned smax[COUT][4];       // per-warp max keys

    const int tb  = blockIdx.z;              // t*B + b
    const int t   = tb >> 5;
    const int tx  = threadIdx.x;             // lane -> channels 2tx, 2tx+1
    const int wid = threadIdx.y;             // 4 warps -> 4 row groups
    const int tid = wid * 32 + tx;

    for (int idx = tid; idx < COUT * 27; idx += 128) {
        int co = idx / 27;
        ws[co * 28 + (idx - co * 27)] = Wt[idx];
    }

    const float* xb = x + tb * (CIN * SPAT);
    const int y0 = blockIdx.y * 16;
    const int x0 = blockIdx.x * 32;
    for (int idx = tid; idx < CIN * 612; idx += 128) {
        int ci  = idx / 612;
        int rem = idx - ci * 612;
        int yy  = rem / 34;
        int xx  = rem - yy * 34;
        int gy = y0 + yy - 1, gx = x0 + xx - 1;
        float v = 0.f;
        if ((unsigned)gy < 64u && (unsigned)gx < 64u) v = xb[ci * SPAT + gy * 64 + gx];
        xs[ci][yy][xx] = v;
    }
    __syncthreads();

    float w0[28], w1[28];
    {
        const float4* p0 = (const float4*)(ws + (2 * tx) * 28);
        const float4* p1 = (const float4*)(ws + (2 * tx + 1) * 28);
#pragma unroll
        for (int q = 0; q < 7; q++) {
            float4 a = p0[q];
            w0[4 * q] = a.x; w0[4 * q + 1] = a.y; w0[4 * q + 2] = a.z; w0[4 * q + 3] = a.w;
            float4 c = p1[q];
            w1[4 * q] = c.x; w1[4 * q + 1] = c.y; w1[4 * q + 2] = c.z; w1[4 * q + 3] = c.w;
        }
    }

    float2* gp = (float2*)g_i + (long)tb * (SPAT * 32);
    float mx0 = -1e30f, mx1 = -1e30f;

#pragma unroll 1
    for (int rr = 0; rr < 4; rr++) {
        const int row = 4 * wid + rr;                       // tile row 0..15
        const int sprow = ((y0 + row) * 64 + x0) * 32;      // float2 base

        float xw[CIN][3][3];                                // [ci][slot][ky]
#pragma unroll
        for (int ci = 0; ci < CIN; ci++)
#pragma unroll
            for (int s = 0; s < 3; s++)
#pragma unroll
                for (int ky = 0; ky < 3; ky++)
                    xw[ci][s][ky] = xs[ci][row + ky][s];

#pragma unroll 1
        for (int c3 = 0; c3 < 30; c3 += 3) {
            STEP(0, 1, 2, c3 + 0, true);
            STEP(1, 2, 0, c3 + 1, true);
            STEP(2, 0, 1, c3 + 2, true);
        }
        STEP(0, 1, 2, 30, true);     // loads col 33 into slot 0
        STEP(1, 2, 0, 31, false);
    }

    unsigned u0 = __float_as_uint(mx0);
    unsigned k0 = ((int)u0 < 0) ? ~u0 : (u0 | 0x80000000u);
    unsigned u1 = __float_as_uint(mx1);
    unsigned k1 = ((int)u1 < 0) ? ~u1 : (u1 | 0x80000000u);
    smax[2 * tx][wid]     = k0;
    smax[2 * tx + 1][wid] = k1;
    __syncthreads();
    if (tid < COUT) {
        unsigned m = smax[tid][0];
        m = max(m, smax[tid][1]); m = max(m, smax[tid][2]); m = max(m, smax[tid][3]);
        atomicMax(&g_thr_keys[t * COUT + tid], m);
    }
}

// ---------------------------------------------------------------------------
// LIF + ASF + WTA + inhibition. WARP = 2 PIXELS: half-warp (16 lanes) covers
// one pixel's 64 channels via one float4 (LDG.128) per lane per t. WTA via
// half-warp REDUX pair. Thresholds decoded in-block (finalize kernel gone).
// No barriers in the t-loop; coalesced store phase at the end.
__global__ void __launch_bounds__(1024, 2) lif_kernel(float* __restrict__ out) {
    __shared__ float4 sth4[160], sih4[160], szs4[160];   // [t*16 + quad]
    __shared__ int    swz[64][11];                       // [pixel][t], pad 11

    const int tx  = threadIdx.x;         // lane
    const int ty  = threadIdx.y;         // warp -> pixel pair
    const int tid = ty * 32 + tx;
    const int b   = blockIdx.x >> 6;     // 64 blocks per batch image
    const int spb = (blockIdx.x & 63) * 64;

    if (tid < N_THR) {                   // decode thresholds (was finalize_thr)
        unsigned k = g_thr_keys[tid];
        unsigned u = (k & 0x80000000u) ? (k & 0x7FFFFFFFu) : ~k;
        float thr  = __uint_as_float(u) + 1e-4f;
        ((float*)sth4)[tid] = thr;
        ((float*)sih4)[tid] = INH * thr;
        ((float*)szs4)[tid] = 11.541560f / thr;   // 8*log2(e)/thr
    }
    __syncthreads();

    const int half  = tx >> 4;           // pixel within pair
    const int li    = tx & 15;           // channel quad
    const int cbase = 4 * li;
    const int sp    = spb + 2 * ty + half;
    const unsigned hmask = half ? 0xFFFF0000u : 0x0000FFFFu;

    const float4* ip = (const float4*)g_i;
    const int pbase = (b * SPAT + sp) * 16 + li;     // float4 index
    const int tstep = B_SZ * SPAT * 16;              // float4 per timestep

    float4 f0 = ip[pbase];
    float4 f1 = ip[pbase + tstep];
    float m0 = 0.f, m1 = 0.f, m2 = 0.f, m3 = 0.f;

#pragma unroll
    for (int t = 0; t < T_STEPS; t++) {
        const float4 iv = (t & 1) ? f1 : f0;
        if (t + 2 < T_STEPS) {                       // depth-2 prefetch
            if (t & 1) f1 = ip[pbase + (t + 2) * tstep];
            else       f0 = ip[pbase + (t + 2) * tstep];
        }
        const float4 th = sth4[t * 16 + li];
        const float4 ih = sih4[t * 16 + li];
        const float4 zs = szs4[t * 16 + li];

        // fast ASF: thr / (1 + exp2(KC - cur*zs)), then LIF decay+input
        float e0, e1, e2, e3, q0, q1, q2, q3;
        float z0 = fmaf(fmaxf(iv.x, 0.f), -zs.x, KC);
        float z1 = fmaf(fmaxf(iv.y, 0.f), -zs.y, KC);
        float z2 = fmaf(fmaxf(iv.z, 0.f), -zs.z, KC);
        float z3 = fmaf(fmaxf(iv.w, 0.f), -zs.w, KC);
        asm("ex2.approx.f32 %0, %1;" : "=f"(e0) : "f"(z0));
        asm("ex2.approx.f32 %0, %1;" : "=f"(e1) : "f"(z1));
        asm("ex2.approx.f32 %0, %1;" : "=f"(e2) : "f"(z2));
        asm("ex2.approx.f32 %0, %1;" : "=f"(e3) : "f"(z3));
        asm("rcp.approx.f32 %0, %1;" : "=f"(q0) : "f"(1.f + e0));
        asm("rcp.approx.f32 %0, %1;" : "=f"(q1) : "f"(1.f + e1));
        asm("rcp.approx.f32 %0, %1;" : "=f"(q2) : "f"(1.f + e2));
        asm("rcp.approx.f32 %0, %1;" : "=f"(q3) : "f"(1.f + e3));

        m0 = fmaf(m0, DECAY, th.x * q0);
        m1 = fmaf(m1, DECAY, th.y * q1);
        m2 = fmaf(m2, DECAY, th.z * q2);
        m3 = fmaf(m3, DECAY, th.w * q3);

        const int s0 = m0 > th.x ? 1 : 0;
        const int s1 = m1 > th.y ? 1 : 0;
        const int s2 = m2 > th.z ? 1 : 0;
        const int s3 = m3 > th.w ? 1 : 0;

        // in-lane candidate scan, ascending channel, strict > keeps first
        float bs = s0 ? m0 : 0.f;
        int   bi = (cbase << 1) | s0;
        float sc = s1 ? m1 : 0.f;
        if (sc > bs) { bs = sc; bi = ((cbase + 1) << 1) | s1; }
        sc = s2 ? m2 : 0.f;
        if (sc > bs) { bs = sc; bi = ((cbase + 2) << 1) | s2; }
        sc = s3 ? m3 : 0.f;
        if (sc > bs) { bs = sc; bi = ((cbase + 3) << 1) | s3; }

        // half-warp argmax: bs >= 0 so raw bits are order-preserving
        const unsigned key  = __float_as_uint(bs);
        const unsigned mk   = __reduce_max_sync(hmask, key);
        const unsigned cand = (key == mk) ? (unsigned)bi : 0x7fffffffu;
        const int      wz   = (int)__reduce_min_sync(hmask, cand);

        const int   wc  = wz >> 1;
        const float any = (float)(wz & 1);           // winner's spike -> any_sp

        const float sn0 = (wc == cbase)     ? (float)s0 : 0.f;
        const float sn1 = (wc == cbase + 1) ? (float)s1 : 0.f;
        const float sn2 = (wc == cbase + 2) ? (float)s2 : 0.f;
        const float sn3 = (wc == cbase + 3) ? (float)s3 : 0.f;

        m0 = (sn0 > 0.f) ? 0.f : fmaf(-ih.x, any, m0);
        m1 = (sn1 > 0.f) ? 0.f : fmaf(-ih.y, any, m1);
        m2 = (sn2 > 0.f) ? 0.f : fmaf(-ih.z, any, m2);
        m3 = (sn3 > 0.f) ? 0.f : fmaf(-ih.w, any, m3);

        if (li == 0) swz[2 * ty + half][t] = wz;
    }
    __syncthreads();

    // store phase: reference layout (t,b,c,h,w); lanes = pixels (coalesced)
    const int obase = (b * COUT + ty) * SPAT + spb + tx;
    const int ostep = B_SZ * COUT * SPAT;
#pragma unroll
    for (int t = 0; t < T_STEPS; t++) {
        const int wa = swz[tx][t];
        const int wb = swz[tx + 32][t];
        const int tb_ = t * ostep;
        out[obase + tb_]                  = (wa == ((ty << 1) | 1))        ? 1.f : 0.f;
        out[obase + tb_ + 32]             = (wb == ((ty << 1) | 1))        ? 1.f : 0.f;
        out[obase + tb_ + 32 * SPAT]      = (wa == (((ty + 32) << 1) | 1)) ? 1.f : 0.f;
        out[obase + tb_ + 32 * SPAT + 32] = (wb == (((ty + 32) << 1) | 1)) ? 1.f : 0.f;
    }
}

// ---------------------------------------------------------------------------
extern "C" void kernel_launch(void* const* d_in, const int* in_sizes, int n_in,
                              void* d_out, int out_size) {
    const float* x = (const float*)d_in[0];
    const float* W = (const float*)d_in[1];
    if (n_in >= 2 && in_sizes[0] == COUT * CIN * 9) {  // defensive order swap
        const float* tmp = x; x = W; W = tmp;
    }

    init_keys<<<1, N_THR>>>();

    dim3 cb(32, 4);
    dim3 cg(2, 4, T_STEPS * B_SZ);
    conv_kernel<<<cg, cb>>>(x, W);

    lif_kernel<<<(B_SZ * SPAT) / 64, dim3(32, 32)>>>((float*)d_out);
}

// round 12
// speedup vs baseline: 1.0455x; 1.0455x over previous
#include <cuda_runtime.h>

#define T_STEPS 10
#define B_SZ    32
#define CIN     3
#define COUT    64
#define SPAT    4096            // 64*64
#define N_THR   (T_STEPS * COUT)
#define DECAY   0.2f
#define INH     1.625f
#define KC      4.6166241f      /* 3.2 * log2(e) */

// Scratch: conv results, CHANNEL-LAST layout (t, b, sp, c).  335.5 MB
__device__ float    g_i[T_STEPS * B_SZ * SPAT * COUT];
__device__ unsigned g_thr_keys[N_THR];   // zero-init at load; self-reset each run
__device__ float4   g_thrv[N_THR];       // {thr, INH*thr, 8*log2e/thr, 0}

// ---------------------------------------------------------------------------
// Conv 3x3, stride 1, pad 1 (R10, proven at the FFMA floor). LANE =
// CHANNEL-PAIR with register weights and a sliding 3x3x3 input window;
// float2 stores -> natively coalesced channel-last output.
#define STEP(S0_, S1_, S2_, C_, DOLOAD_) do {                                 \
    float a0 = 0.f, a1 = 0.f, a2 = 0.f, b0 = 0.f, b1 = 0.f, b2 = 0.f;         \
    const int SL_[3] = {S0_, S1_, S2_};                                       \
    _Pragma("unroll")                                                         \
    for (int ky = 0; ky < 3; ky++)                                            \
        _Pragma("unroll")                                                     \
        for (int kx = 0; kx < 3; kx++) {                                      \
            const int j = ky * 3 + kx;                                        \
            const int s = SL_[kx];                                            \
            a0 = fmaf(xw[0][s][ky], w0[j],      a0);                          \
            a1 = fmaf(xw[1][s][ky], w0[j + 9],  a1);                          \
            a2 = fmaf(xw[2][s][ky], w0[j + 18], a2);                          \
            b0 = fmaf(xw[0][s][ky], w1[j],      b0);                          \
            b1 = fmaf(xw[1][s][ky], w1[j + 9],  b1);                          \
            b2 = fmaf(xw[2][s][ky], w1[j + 18], b2);                          \
        }                                                                     \
    const float v0 = (a0 + a1) + a2;                                          \
    const float v1 = (b0 + b1) + b2;                                          \
    gp[sprow + (C_) * 32 + tx] = make_float2(v0, v1);                         \
    mx0 = fmaxf(mx0, v0);                                                     \
    mx1 = fmaxf(mx1, v1);                                                     \
    if (DOLOAD_) {                                                            \
        _Pragma("unroll")                                                     \
        for (int ci = 0; ci < CIN; ci++)                                      \
            _Pragma("unroll")                                                 \
            for (int ky = 0; ky < 3; ky++)                                    \
                xw[ci][S0_][ky] = xs[ci][row + ky][(C_) + 3];                 \
    }                                                                         \
} while (0)

__global__ void __launch_bounds__(128) conv_kernel(const float* __restrict__ x,
                                                   const float* __restrict__ Wt) {
    __shared__ float    xs[CIN][18][34];     // 32x16 tile + halo
    __shared__ float    ws[COUT * 28];       // 27 weights + 1 pad per channel
    __shared__ unsigned smax[COUT][4];       // per-warp max keys

    const int tb  = blockIdx.z;              // t*B + b
    const int t   = tb >> 5;
    const int tx  = threadIdx.x;             // lane -> channels 2tx, 2tx+1
    const int wid = threadIdx.y;             // 4 warps -> 4 row groups
    const int tid = wid * 32 + tx;

    for (int idx = tid; idx < COUT * 27; idx += 128) {
        int co = idx / 27;
        ws[co * 28 + (idx - co * 27)] = Wt[idx];
    }

    const float* xb = x + tb * (CIN * SPAT);
    const int y0 = blockIdx.y * 16;
    const int x0 = blockIdx.x * 32;
    for (int idx = tid; idx < CIN * 612; idx += 128) {
        int ci  = idx / 612;
        int rem = idx - ci * 612;
        int yy  = rem / 34;
        int xx  = rem - yy * 34;
        int gy = y0 + yy - 1, gx = x0 + xx - 1;
        float v = 0.f;
        if ((unsigned)gy < 64u && (unsigned)gx < 64u) v = xb[ci * SPAT + gy * 64 + gx];
        xs[ci][yy][xx] = v;
    }
    __syncthreads();

    float w0[28], w1[28];
    {
        const float4* p0 = (const float4*)(ws + (2 * tx) * 28);
        const float4* p1 = (const float4*)(ws + (2 * tx + 1) * 28);
#pragma unroll
        for (int q = 0; q < 7; q++) {
            float4 a = p0[q];
            w0[4 * q] = a.x; w0[4 * q + 1] = a.y; w0[4 * q + 2] = a.z; w0[4 * q + 3] = a.w;
            float4 c = p1[q];
            w1[4 * q] = c.x; w1[4 * q + 1] = c.y; w1[4 * q + 2] = c.z; w1[4 * q + 3] = c.w;
        }
    }

    float2* gp = (float2*)g_i + (long)tb * (SPAT * 32);
    float mx0 = -1e30f, mx1 = -1e30f;

#pragma unroll 1
    for (int rr = 0; rr < 4; rr++) {
        const int row = 4 * wid + rr;                       // tile row 0..15
        const int sprow = ((y0 + row) * 64 + x0) * 32;      // float2 base

        float xw[CIN][3][3];                                // [ci][slot][ky]
#pragma unroll
        for (int ci = 0; ci < CIN; ci++)
#pragma unroll
            for (int s = 0; s < 3; s++)
#pragma unroll
                for (int ky = 0; ky < 3; ky++)
                    xw[ci][s][ky] = xs[ci][row + ky][s];

#pragma unroll 1
        for (int c3 = 0; c3 < 30; c3 += 3) {
            STEP(0, 1, 2, c3 + 0, true);
            STEP(1, 2, 0, c3 + 1, true);
            STEP(2, 0, 1, c3 + 2, true);
        }
        STEP(0, 1, 2, 30, true);     // loads col 33 into slot 0
        STEP(1, 2, 0, 31, false);
    }

    unsigned u0 = __float_as_uint(mx0);
    unsigned k0 = ((int)u0 < 0) ? ~u0 : (u0 | 0x80000000u);
    unsigned u1 = __float_as_uint(mx1);
    unsigned k1 = ((int)u1 < 0) ? ~u1 : (u1 | 0x80000000u);
    smax[2 * tx][wid]     = k0;
    smax[2 * tx + 1][wid] = k1;
    __syncthreads();
    if (tid < COUT) {
        unsigned m = smax[tid][0];
        m = max(m, smax[tid][1]); m = max(m, smax[tid][2]); m = max(m, smax[tid][3]);
        atomicMax(&g_thr_keys[t * COUT + tid], m);
    }
}

// ---------------------------------------------------------------------------
// Decode per-(t,c) max keys -> threshold vectors, then RESET the keys so the
// next graph replay starts from zero (replaces the init_keys kernel).
__global__ void finalize_thr() {
    int i = blockIdx.x * blockDim.x + threadIdx.x;
    if (i < N_THR) {
        unsigned k = g_thr_keys[i];
        unsigned u = (k & 0x80000000u) ? (k & 0x7FFFFFFFu) : ~k;
        float thr  = __uint_as_float(u) + 1e-4f;
        float zs   = 11.541560f / thr;        // 8*log2(e)/thr
        g_thrv[i]  = make_float4(thr, INH * thr, zs, 0.f);
        g_thr_keys[i] = 0u;                   // self-reset for next replay
    }
}

// ---------------------------------------------------------------------------
// LIF + ASF + WTA + inhibition (R10, proven): warp-per-pixel on channel-last
// data, lane owns channels 2tx/2tx+1 (one coalesced float2 load per t), WTA
// via 2 REDUX ops, mem in regs. No barriers/smem tiles in the t-loop.
__global__ void __launch_bounds__(1024) lif_kernel(float* __restrict__ out) {
    __shared__ float2 sth[320], sih[320], szs[320];  // [t*32 + pair]
    __shared__ int    swz[32][11];                   // [pixel][t], pad 11

    const int tx  = threadIdx.x;         // lane -> channel pair
    const int ty  = threadIdx.y;         // warp -> pixel
    const int tid = ty * 32 + tx;
    const int b   = blockIdx.x >> 7;     // 128 blocks per batch image
    const int spb = (blockIdx.x & 127) * 32;

    if (tid < 320) {
        int t = tid >> 5, p = tid & 31;
        float4 a = g_thrv[t * COUT + 2 * p];
        float4 c = g_thrv[t * COUT + 2 * p + 1];
        sth[tid] = make_float2(a.x, c.x);
        sih[tid] = make_float2(a.y, c.y);
        szs[tid] = make_float2(a.z, c.z);
    }
    __syncthreads();

    const int sp    = spb + ty;
    const int c0    = 2 * tx, c1 = 2 * tx + 1;
    const float2* ip = (const float2*)g_i;
    const int pbase = (b * SPAT + sp) * 32 + tx;     // float2 index
    const int tstep = B_SZ * SPAT * 32;              // float2 per timestep

    float2 b0 = ip[pbase];
    float2 b1 = ip[pbase + tstep];
    float m0 = 0.f, m1 = 0.f;

#pragma unroll
    for (int t = 0; t < T_STEPS; t++) {
        const float2 iv = (t & 1) ? b1 : b0;
        if (t + 2 < T_STEPS) {                       // depth-2 prefetch
            if (t & 1) b1 = ip[pbase + (t + 2) * tstep];
            else       b0 = ip[pbase + (t + 2) * tstep];
        }
        const float2 th = sth[t * 32 + tx];
        const float2 ih = sih[t * 32 + tx];
        const float2 zs = szs[t * 32 + tx];

        // fast ASF: thr / (1 + exp2(KC - cur*zs))
        float zn0 = fmaf(fmaxf(iv.x, 0.f), -zs.x, KC);
        float zn1 = fmaf(fmaxf(iv.y, 0.f), -zs.y, KC);
        float e0, e1, q0, q1;
        asm("ex2.approx.f32 %0, %1;" : "=f"(e0) : "f"(zn0));
        asm("ex2.approx.f32 %0, %1;" : "=f"(e1) : "f"(zn1));
        asm("rcp.approx.f32 %0, %1;" : "=f"(q0) : "f"(1.f + e0));
        asm("rcp.approx.f32 %0, %1;" : "=f"(q1) : "f"(1.f + e1));

        m0 = fmaf(m0, DECAY, th.x * q0);
        m1 = fmaf(m1, DECAY, th.y * q1);

        const int   s0i = m0 > th.x ? 1 : 0;
        const int   s1i = m1 > th.y ? 1 : 0;
        const float sc0 = s0i ? m0 : 0.f;
        const float sc1 = s1i ? m1 : 0.f;

        // per-lane candidate; lower channel wins ties (argmax-first semantics)
        float bs; int bi;
        if (sc0 >= sc1) { bs = sc0; bi = (c0 << 1) | s0i; }
        else            { bs = sc1; bi = (c1 << 1) | s1i; }

        unsigned ub   = __float_as_uint(bs);
        unsigned key  = ((int)ub < 0) ? ~ub : (ub | 0x80000000u);
        unsigned mk   = __reduce_max_sync(0xffffffffu, key);
        unsigned cand = (key == mk) ? (unsigned)bi : 0x7fffffffu;
        const int wz  = (int)__reduce_min_sync(0xffffffffu, cand);

        const int   wc  = wz >> 1;
        const float any = (float)(wz & 1);            // winner's spike -> any_sp

        const float sn0 = (wc == c0) ? (float)s0i : 0.f;
        const float sn1 = (wc == c1) ? (float)s1i : 0.f;

        m0 = (sn0 > 0.f) ? 0.f : fmaf(-ih.x, any, m0);
        m1 = (sn1 > 0.f) ? 0.f : fmaf(-ih.y, any, m1);

        if (tx == 0) swz[ty][t] = wz;
    }
    __syncthreads();

    // store phase: reference layout (t,b,c,h,w); lanes = pixels (coalesced)
    const int obase = (b * COUT) * SPAT + spb + tx;
    const int ostep = B_SZ * COUT * SPAT;
#pragma unroll
    for (int t = 0; t < T_STEPS; t++) {
        const int w = swz[tx][t];
        out[obase + t * ostep + ty * SPAT]        = (w == ((ty << 1) | 1))        ? 1.f : 0.f;
        out[obase + t * ostep + (ty + 32) * SPAT] = (w == (((ty + 32) << 1) | 1)) ? 1.f : 0.f;
    }
}

// ---------------------------------------------------------------------------
extern "C" void kernel_launch(void* const* d_in, const int* in_sizes, int n_in,
                              void* d_out, int out_size) {
    const float* x = (const float*)d_in[0];
    const float* W = (const float*)d_in[1];
    if (n_in >= 2 && in_sizes[0] == COUT * CIN * 9) {  // defensive order swap
        const float* tmp = x; x = W; W = tmp;
    }

    dim3 cb(32, 4);
    dim3 cg(2, 4, T_STEPS * B_SZ);
    conv_kernel<<<cg, cb>>>(x, W);

    finalize_thr<<<1, N_THR>>>();

    lif_kernel<<<(B_SZ * SPAT) / 32, dim3(32, 32)>>>((float*)d_out);
}